// round 3
// baseline (speedup 1.0000x reference)
#include <cuda_runtime.h>

// LIF recurrence, forward spikes only.
// x: [T=32, B, D] fp32, out: same shape, spikes in {0.0, 1.0}.
//
// Recurrence per independent chain:
//   mem_t = decayed_{t-1} + x_t
//   spike_t = mem_t > 0.5
//   decayed_t = spike_t ? 0 : mem_t * 0.25        (carried state: 4 regs only)
// decayed_{-1} = 0 makes t=0 a regular iteration.
//
// Pure touch-once HBM stream (268 MB total). Chunk-16 load hoist: each warp
// puts 8 KB of __ldcs loads in flight per burst, then runs the dependent
// compute + __stcs store phase. MLP/warp = 16.

#define THRESH 0.5f
#define DECAY  0.25f

__global__ __launch_bounds__(256) void lif_kernel(
    const float4* __restrict__ x,
    float4* __restrict__ out,
    int chains4)   // BD / 4
{
    int i = blockIdx.x * blockDim.x + threadIdx.x;
    const float4* xp = x + i;
    float4*       op = out + i;

    float4 dec = make_float4(0.0f, 0.0f, 0.0f, 0.0f);

    #pragma unroll 1
    for (int c = 0; c < 2; c++) {          // 2 chunks of 16 timesteps
        float4 xt[16];
        #pragma unroll
        for (int k = 0; k < 16; k++)
            xt[k] = __ldcs(xp + (long)k * chains4);

        #pragma unroll
        for (int k = 0; k < 16; k++) {
            float4 m, s;
            m.x = dec.x + xt[k].x;
            m.y = dec.y + xt[k].y;
            m.z = dec.z + xt[k].z;
            m.w = dec.w + xt[k].w;

            s.x = (m.x > THRESH) ? 1.0f : 0.0f;
            s.y = (m.y > THRESH) ? 1.0f : 0.0f;
            s.z = (m.z > THRESH) ? 1.0f : 0.0f;
            s.w = (m.w > THRESH) ? 1.0f : 0.0f;

            dec.x = (m.x > THRESH) ? 0.0f : m.x * DECAY;
            dec.y = (m.y > THRESH) ? 0.0f : m.y * DECAY;
            dec.z = (m.z > THRESH) ? 0.0f : m.z * DECAY;
            dec.w = (m.w > THRESH) ? 0.0f : m.w * DECAY;

            __stcs(op + (long)k * chains4, s);
        }
        xp += 16L * chains4;
        op += 16L * chains4;
    }
}

extern "C" void kernel_launch(void* const* d_in, const int* in_sizes, int n_in,
                              void* d_out, int out_size)
{
    const float* x = (const float*)d_in[0];
    float* out = (float*)d_out;

    const int T = 32;
    int total = in_sizes[0];        // T * B * D
    int BD = total / T;             // 1,048,576
    int chains4 = BD / 4;           // 262,144

    int threads = 256;
    int blocks = chains4 / threads; // exact: 1024
    lif_kernel<<<blocks, threads>>>((const float4*)x, (float4*)out, chains4);
}

// round 4
// speedup vs baseline: 1.0056x; 1.0056x over previous
#include <cuda_runtime.h>

// LIF recurrence, forward spikes only.
// x: [T=32, B, D] fp32, out: same shape, spikes in {0.0, 1.0}.
//
//   mem_t   = dec_{t-1} + x_t
//   spike_t = mem_t > 0.5
//   dec_t   = spike_t ? 0 : mem_t * 0.25      (carried state, dec_{-1}=0)
//
// Touch-once HBM stream (268 MB). R3 showed occ*MLP is conserved when buying
// MLP with registers; the limiter is load-issue duty cycle. Fix: explicit
// software pipeline — two 8-deep float4 buffers, loads of chunk c+1 issued
// BEFORE compute+store of chunk c, fully unrolled (no backward branch blocks
// hoisting). Load pipe never drains.

#define THRESH 0.5f
#define DECAY  0.25f

__device__ __forceinline__ void load8(float4 (&b)[8], const float4* __restrict__ p,
                                      long st)
{
    #pragma unroll
    for (int k = 0; k < 8; k++)
        b[k] = __ldcs(p + (long)k * st);
}

__device__ __forceinline__ void comp8(const float4 (&b)[8], float4& dec,
                                      float4* __restrict__ op, long st)
{
    #pragma unroll
    for (int k = 0; k < 8; k++) {
        float4 m, s;
        m.x = dec.x + b[k].x;
        m.y = dec.y + b[k].y;
        m.z = dec.z + b[k].z;
        m.w = dec.w + b[k].w;

        s.x = (m.x > THRESH) ? 1.0f : 0.0f;
        s.y = (m.y > THRESH) ? 1.0f : 0.0f;
        s.z = (m.z > THRESH) ? 1.0f : 0.0f;
        s.w = (m.w > THRESH) ? 1.0f : 0.0f;

        dec.x = (m.x > THRESH) ? 0.0f : m.x * DECAY;
        dec.y = (m.y > THRESH) ? 0.0f : m.y * DECAY;
        dec.z = (m.z > THRESH) ? 0.0f : m.z * DECAY;
        dec.w = (m.w > THRESH) ? 0.0f : m.w * DECAY;

        __stcs(op + (long)k * st, s);
    }
}

__global__ __launch_bounds__(256) void lif_kernel(
    const float4* __restrict__ x,
    float4* __restrict__ out,
    int chains4)   // BD / 4
{
    int i = blockIdx.x * blockDim.x + threadIdx.x;
    const long st = chains4;
    const float4* __restrict__ xp = x + i;
    float4* __restrict__       op = out + i;

    float4 A[8], B[8];
    float4 dec = make_float4(0.0f, 0.0f, 0.0f, 0.0f);

    load8(A, xp, st);                    // t 0..7   in flight
    load8(B, xp + 8 * st, st);           // t 8..15  in flight  (16 deep)
    comp8(A, dec, op, st);               // compute t0..7 while B lands
    load8(A, xp + 16 * st, st);          // t 16..23 in flight
    comp8(B, dec, op + 8 * st, st);
    load8(B, xp + 24 * st, st);          // t 24..31 in flight
    comp8(A, dec, op + 16 * st, st);
    comp8(B, dec, op + 24 * st, st);
}

extern "C" void kernel_launch(void* const* d_in, const int* in_sizes, int n_in,
                              void* d_out, int out_size)
{
    const float* x = (const float*)d_in[0];
    float* out = (float*)d_out;

    const int T = 32;
    int total = in_sizes[0];        // T * B * D
    int BD = total / T;             // 1,048,576
    int chains4 = BD / 4;           // 262,144

    int threads = 256;
    int blocks = chains4 / threads; // exact: 1024
    lif_kernel<<<blocks, threads>>>((const float4*)x, (float4*)out, chains4);
}